// round 4
// baseline (speedup 1.0000x reference)
#include <cuda_runtime.h>
#include <cuda_bf16.h>
#include <math.h>

#define NNODES 512
#define EPSF 1e-8f

// static device scratch (allocated at module load, not at runtime)
__device__ float g_in1t[3][NNODES * 32];   // [i][b*32+c]
__device__ float g_in2t[5][NNODES * 32];   // [i][b*32+c]
__device__ float g_geo[NNODES * NNODES * 9]; // [a*512+b][ux,uy,uz,y0..y4,mask]

struct Params {
    const float* __restrict__ in0;   // [N,C,1]
    const float* __restrict__ in1;   // [N,C,3]
    const float* __restrict__ in2;   // [N,C,5]
    const float* __restrict__ rbf;   // [N,N,R]
    const float* __restrict__ rij;   // [N,N,3]
    const float* __restrict__ w1[5]; // [R,R]
    const float* __restrict__ b1[5]; // [R]
    const float* __restrict__ w2[5]; // [C,R]
    const float* __restrict__ b2[5]; // [C]
    float* __restrict__ out;
};

__global__ __launch_bounds__(256) void prep_kernel(
    const float* __restrict__ rij,
    const float* __restrict__ in1,
    const float* __restrict__ in2)
{
    int idx = blockIdx.x * 256 + threadIdx.x;   // 0 .. 262143
    if (idx < NNODES * 32) {
        #pragma unroll
        for (int i = 0; i < 3; i++) g_in1t[i][idx] = in1[idx * 3 + i];
        #pragma unroll
        for (int i = 0; i < 5; i++) g_in2t[i][idx] = in2[idx * 5 + i];
    }
    const float inv_c2 = 0.28867513459481287f;  // 1/(2*sqrt(3))
    float rx = rij[idx * 3 + 0];
    float ry = rij[idx * 3 + 1];
    float rz = rij[idx * 3 + 2];
    float n2 = rx * rx + ry * ry + rz * rz;
    float nrm = sqrtf(n2);
    float invn = 1.f / (nrm + EPSF);
    float mask = (nrm >= EPSF) ? 1.f : 0.f;
    float ir2 = 1.f / fmaxf(n2, EPSF);
    float* g = g_geo + (size_t)idx * 9;
    g[0] = rx * invn; g[1] = ry * invn; g[2] = rz * invn;
    g[3] = rx * ry * ir2;
    g[4] = ry * rz * ir2;
    g[5] = (2.f * rz * rz - rx * rx - ry * ry) * ir2 * inv_c2;
    g[6] = rz * rx * ir2;
    g[7] = (rx * rx - ry * ry) * 0.5f * ir2;
    g[8] = mask;
}

// 5 warps = 5 filters. lane j owns row j of W1_f, lane c owns row c of W2_f.
__global__ __launch_bounds__(160, 4) void tfn_kernel(Params p) {
    __shared__ float rbf_s[2][8 * 32];  // double-buffered [b][r]
    __shared__ float geo_s[2][8 * 9];   // double-buffered
    __shared__ float hid_s[8 * 160];    // [b][f*32+j]
    __shared__ float rad_s[8 * 160];    // [b][f*32+c]

    const int tid  = threadIdx.x;
    const int lane = tid & 31;
    const int f    = tid >> 5;
    const int a    = blockIdx.x;
    const int c    = lane;

    // ---- weights into registers ----
    float w1r[32], w2r[32];
    {
        const float4* w1p = (const float4*)(p.w1[f] + lane * 32);
        const float4* w2p = (const float4*)(p.w2[f] + lane * 32);
        #pragma unroll
        for (int k = 0; k < 8; k++) {
            float4 t1 = w1p[k];
            float4 t2 = w2p[k];
            w1r[4*k+0] = t1.x; w1r[4*k+1] = t1.y; w1r[4*k+2] = t1.z; w1r[4*k+3] = t1.w;
            w2r[4*k+0] = t2.x; w2r[4*k+1] = t2.y; w2r[4*k+2] = t2.z; w2r[4*k+3] = t2.w;
        }
    }
    const float b1r = p.b1[f][lane];
    const float b2r = p.b2[f][lane];

    float acc0 = 0.f, acc1 = 0.f, acc2 = 0.f, acc3 = 0.f, acc4 = 0.f;

    // ---- preload tile 0 ----
    if (tid < 64) {
        ((float4*)rbf_s[0])[tid] =
            ((const float4*)(p.rbf + (size_t)a * NNODES * 32))[tid];
    } else if (tid < 136) {
        geo_s[0][tid - 64] = g_geo[(size_t)a * NNODES * 9 + (tid - 64)];
    }
    __syncthreads();

    int buf = 0;
    for (int t = 0; t < 64; t++) {
        const int b0 = t * 8;
        const int nbuf = buf ^ 1;

        // issue prefetch for next tile into registers (stored after accumulate)
        float4 pre_rbf;
        float pre_geo;
        if (t < 63) {
            if (tid < 64) {
                pre_rbf = ((const float4*)(p.rbf + ((size_t)a * NNODES + b0 + 8) * 32))[tid];
            } else if (tid < 136) {
                pre_geo = g_geo[((size_t)a * NNODES + b0 + 8) * 9 + (tid - 64)];
            }
        }

        const float* rb = rbf_s[buf];
        const float* ge = geo_s[buf];

        // ---- stage1: hidden = relu(b1 + W1 @ rbf) ----
        #pragma unroll 4
        for (int b = 0; b < 8; b++) {
            float s = b1r;
            const float4* x4 = (const float4*)(rb + b * 32);
            #pragma unroll
            for (int k = 0; k < 8; k++) {
                float4 x = x4[k];
                s = fmaf(w1r[4*k+0], x.x, s);
                s = fmaf(w1r[4*k+1], x.y, s);
                s = fmaf(w1r[4*k+2], x.z, s);
                s = fmaf(w1r[4*k+3], x.w, s);
            }
            hid_s[b * 160 + f * 32 + lane] = fmaxf(s, 0.f);
        }
        __syncwarp();   // stage2 of filter f reads only filter f's hidden

        // ---- stage2: rad = b2 + W2 @ hidden ----
        #pragma unroll 4
        for (int b = 0; b < 8; b++) {
            float s = b2r;
            const float4* h4 = (const float4*)(hid_s + b * 160 + f * 32);
            #pragma unroll
            for (int k = 0; k < 8; k++) {
                float4 x = h4[k];
                s = fmaf(w2r[4*k+0], x.x, s);
                s = fmaf(w2r[4*k+1], x.y, s);
                s = fmaf(w2r[4*k+2], x.z, s);
                s = fmaf(w2r[4*k+3], x.w, s);
            }
            rad_s[b * 160 + f * 32 + lane] = s;
        }
        __syncthreads();   // rad ready for cross-filter consumption

        // ---- accumulate: each warp owns one output group ----
        if (f == 0) {
            // o2_s += r00 * in2
            #pragma unroll
            for (int b = 0; b < 8; b++) {
                int gi = (b0 + b) * 32 + c;
                float r00 = rad_s[b * 160 + c];
                acc0 = fmaf(r00, g_in2t[0][gi], acc0);
                acc1 = fmaf(r00, g_in2t[1][gi], acc1);
                acc2 = fmaf(r00, g_in2t[2][gi], acc2);
                acc3 = fmaf(r00, g_in2t[3][gi], acc3);
                acc4 = fmaf(r00, g_in2t[4][gi], acc4);
            }
        } else if (f == 1) {
            // o2_a += (r02*mask) * y2 * x0
            #pragma unroll
            for (int b = 0; b < 8; b++) {
                const float* g = ge + b * 9;
                float rx = rad_s[b * 160 + 64 + c] * g[8]
                         * p.in0[(size_t)(b0 + b) * 32 + c];
                acc0 = fmaf(rx, g[3], acc0);
                acc1 = fmaf(rx, g[4], acc1);
                acc2 = fmaf(rx, g[5], acc2);
                acc3 = fmaf(rx, g[6], acc3);
                acc4 = fmaf(rx, g[7], acc4);
            }
        } else if (f == 2) {
            // o1_s += r00 * in1 ; o0_s += r00 * in0
            #pragma unroll
            for (int b = 0; b < 8; b++) {
                int gi = (b0 + b) * 32 + c;
                float r00 = rad_s[b * 160 + c];
                acc0 = fmaf(r00, g_in1t[0][gi], acc0);
                acc1 = fmaf(r00, g_in1t[1][gi], acc1);
                acc2 = fmaf(r00, g_in1t[2][gi], acc2);
                acc3 = fmaf(r00, p.in0[gi], acc3);
            }
        } else if (f == 3) {
            // o1_c += (r11*mask)*(u x v) ; o0_b += (r10*mask)*(u . v)
            #pragma unroll
            for (int b = 0; b < 8; b++) {
                int gi = (b0 + b) * 32 + c;
                const float* g = ge + b * 9;
                float mask = g[8];
                float r10 = rad_s[b * 160 + 96 + c] * mask;
                float r11 = rad_s[b * 160 + 128 + c] * mask;
                float v0 = g_in1t[0][gi];
                float v1 = g_in1t[1][gi];
                float v2 = g_in1t[2][gi];
                float ux = g[0], uy = g[1], uz = g[2];
                acc0 = fmaf(r11, uy * v2 - uz * v1, acc0);
                acc1 = fmaf(r11, uz * v0 - ux * v2, acc1);
                acc2 = fmaf(r11, ux * v1 - uy * v0, acc2);
                acc3 = fmaf(r10, ux * v0 + uy * v1 + uz * v2, acc3);
            }
        } else {
            // o1_a += (r01*mask) * u * x0
            #pragma unroll
            for (int b = 0; b < 8; b++) {
                const float* g = ge + b * 9;
                float rx = rad_s[b * 160 + 32 + c] * g[8]
                         * p.in0[(size_t)(b0 + b) * 32 + c];
                acc0 = fmaf(rx, g[0], acc0);
                acc1 = fmaf(rx, g[1], acc1);
                acc2 = fmaf(rx, g[2], acc2);
            }
        }

        // commit prefetched data to the alternate buffers
        if (t < 63) {
            if (tid < 64) {
                ((float4*)rbf_s[nbuf])[tid] = pre_rbf;
            } else if (tid < 136) {
                geo_s[nbuf][tid - 64] = pre_geo;
            }
        }
        __syncthreads();
        buf = nbuf;
    }

    // ---- epilogue: each warp writes its own components ----
    float* out = p.out;
    if (f == 0) {          // o2_s  [1,a,c,:]
        size_t base = 180224 + (((size_t)(NNODES + a)) * 32 + c) * 5;
        out[base + 0] = acc0; out[base + 1] = acc1; out[base + 2] = acc2;
        out[base + 3] = acc3; out[base + 4] = acc4;
    } else if (f == 1) {   // o2_a  [0,a,c,:]
        size_t base = 180224 + (((size_t)a) * 32 + c) * 5;
        out[base + 0] = acc0; out[base + 1] = acc1; out[base + 2] = acc2;
        out[base + 3] = acc3; out[base + 4] = acc4;
    } else if (f == 2) {   // o1_s [1,...] + o0_s [0,...]
        size_t base = 32768 + (((size_t)(NNODES + a)) * 32 + c) * 3;
        out[base + 0] = acc0; out[base + 1] = acc1; out[base + 2] = acc2;
        out[(size_t)a * 32 + c] = acc3;
    } else if (f == 3) {   // o1_c [2,...] + o0_b [1,...]
        size_t base = 32768 + (((size_t)(2 * NNODES + a)) * 32 + c) * 3;
        out[base + 0] = acc0; out[base + 1] = acc1; out[base + 2] = acc2;
        out[16384 + (size_t)a * 32 + c] = acc3;
    } else {               // o1_a [0,...]
        size_t base = 32768 + (((size_t)a) * 32 + c) * 3;
        out[base + 0] = acc0; out[base + 1] = acc1; out[base + 2] = acc2;
    }
}

extern "C" void kernel_launch(void* const* d_in, const int* in_sizes, int n_in,
                              void* d_out, int out_size) {
    Params p;
    p.in0 = (const float*)d_in[0];
    p.in1 = (const float*)d_in[1];
    p.in2 = (const float*)d_in[2];
    p.rbf = (const float*)d_in[3];
    p.rij = (const float*)d_in[4];
    for (int f = 0; f < 5; f++) {
        p.w1[f] = (const float*)d_in[5 + 4 * f];
        p.b1[f] = (const float*)d_in[6 + 4 * f];
        p.w2[f] = (const float*)d_in[7 + 4 * f];
        p.b2[f] = (const float*)d_in[8 + 4 * f];
    }
    p.out = (float*)d_out;

    prep_kernel<<<(NNODES * NNODES) / 256, 256>>>(p.rij, p.in1, p.in2);
    tfn_kernel<<<NNODES, 160>>>(p);
}

// round 8
// speedup vs baseline: 1.0003x; 1.0003x over previous
#include <cuda_runtime.h>
#include <cuda_bf16.h>
#include <math.h>
#include <stdint.h>

typedef unsigned long long u64;

#define NNODES 512
#define EPSF 1e-8f

// static device scratch
__device__ __align__(16) float g_in1t[3][NNODES * 32];        // [i][b*32+c]
__device__ __align__(16) float g_in2t[5][NNODES * 32];        // [i][b*32+c]
__device__ __align__(16) float g_geo[(size_t)NNODES * NNODES * 12]; // pitch 12

struct Params {
    const float* __restrict__ in0;
    const float* __restrict__ in1;
    const float* __restrict__ in2;
    const float* __restrict__ rbf;
    const float* __restrict__ rij;
    const float* __restrict__ w1[5];
    const float* __restrict__ b1[5];
    const float* __restrict__ w2[5];
    const float* __restrict__ b2[5];
    float* __restrict__ out;
};

// ---- packed f32x2 helpers (b64 regs, "l" constraints) ----
__device__ __forceinline__ u64 pk2(float lo, float hi) {
    u64 d;
    asm("mov.b64 %0, {%1, %2};" : "=l"(d) : "f"(lo), "f"(hi));
    return d;
}
__device__ __forceinline__ void upk2(u64 d, float& lo, float& hi) {
    asm("mov.b64 {%0, %1}, %2;" : "=f"(lo), "=f"(hi) : "l"(d));
}
__device__ __forceinline__ u64 f2fma(u64 a, u64 b, u64 c) {
    u64 d;
    asm("fma.rn.f32x2 %0, %1, %2, %3;" : "=l"(d) : "l"(a), "l"(b), "l"(c));
    return d;
}
__device__ __forceinline__ u64 f2add(u64 a, u64 b) {
    u64 d;
    asm("add.rn.f32x2 %0, %1, %2;" : "=l"(d) : "l"(a), "l"(b));
    return d;
}
__device__ __forceinline__ void cpa16(void* dst, const void* src) {
    unsigned int d = (unsigned int)__cvta_generic_to_shared(dst);
    asm volatile("cp.async.cg.shared.global [%0], [%1], 16;" :: "r"(d), "l"(src));
}
__device__ __forceinline__ void cpa_commit() {
    asm volatile("cp.async.commit_group;");
}
__device__ __forceinline__ void cpa_wait0() {
    asm volatile("cp.async.wait_group 0;" ::: "memory");
}

__global__ __launch_bounds__(256) void prep_kernel(
    const float* __restrict__ rij,
    const float* __restrict__ in1,
    const float* __restrict__ in2)
{
    int idx = blockIdx.x * 256 + threadIdx.x;  // 0 .. N*N-1
    if (idx < NNODES * 32) {
        #pragma unroll
        for (int i = 0; i < 3; i++) g_in1t[i][idx] = in1[idx * 3 + i];
        #pragma unroll
        for (int i = 0; i < 5; i++) g_in2t[i][idx] = in2[idx * 5 + i];
    }
    const float inv_c2 = 0.28867513459481287f;  // 1/(2*sqrt(3))
    float rx = rij[idx * 3 + 0];
    float ry = rij[idx * 3 + 1];
    float rz = rij[idx * 3 + 2];
    float n2 = rx * rx + ry * ry + rz * rz;
    float nrm = sqrtf(n2);
    float invn = 1.f / (nrm + EPSF);
    float mask = (nrm >= EPSF) ? 1.f : 0.f;
    float ir2 = 1.f / fmaxf(n2, EPSF);
    float* g = g_geo + (size_t)idx * 12;
    g[0] = rx * invn; g[1] = ry * invn; g[2] = rz * invn;
    g[3] = rx * ry * ir2;
    g[4] = ry * rz * ir2;
    g[5] = (2.f * rz * rz - rx * rx - ry * ry) * ir2 * inv_c2;
    g[6] = rz * rx * ir2;
    g[7] = (rx * rx - ry * ry) * 0.5f * ir2;
    g[8] = mask;
    g[9] = 0.f; g[10] = 0.f; g[11] = 0.f;
}

// accumulate one 16-neighbor tile for this warp's output group f
__device__ __forceinline__ void do_acc(
    int f, int c, int b0,
    const float* __restrict__ ge,   // geo_s slot  [16*12]
    const float* __restrict__ i0,   // in0_s slot  [16*32]
    const float* __restrict__ rs,   // rad_s buf   [16*160]
    float* acc)
{
    if (f == 0) {            // o2_s += r00 * in2
        #pragma unroll 4
        for (int b = 0; b < 16; b++) {
            int gi = (b0 + b) * 32 + c;
            float r00 = rs[b * 160 + c];
            acc[0] = fmaf(r00, g_in2t[0][gi], acc[0]);
            acc[1] = fmaf(r00, g_in2t[1][gi], acc[1]);
            acc[2] = fmaf(r00, g_in2t[2][gi], acc[2]);
            acc[3] = fmaf(r00, g_in2t[3][gi], acc[3]);
            acc[4] = fmaf(r00, g_in2t[4][gi], acc[4]);
        }
    } else if (f == 1) {     // o2_a += (r02*mask) * y2 * x0
        #pragma unroll 4
        for (int b = 0; b < 16; b++) {
            const float* g = ge + b * 12;
            float rx = rs[b * 160 + 64 + c] * g[8] * i0[b * 32 + c];
            acc[0] = fmaf(rx, g[3], acc[0]);
            acc[1] = fmaf(rx, g[4], acc[1]);
            acc[2] = fmaf(rx, g[5], acc[2]);
            acc[3] = fmaf(rx, g[6], acc[3]);
            acc[4] = fmaf(rx, g[7], acc[4]);
        }
    } else if (f == 2) {     // o1_s += r00 * in1 ; o0_s += r00 * in0
        #pragma unroll 4
        for (int b = 0; b < 16; b++) {
            int gi = (b0 + b) * 32 + c;
            float r00 = rs[b * 160 + c];
            acc[0] = fmaf(r00, g_in1t[0][gi], acc[0]);
            acc[1] = fmaf(r00, g_in1t[1][gi], acc[1]);
            acc[2] = fmaf(r00, g_in1t[2][gi], acc[2]);
            acc[3] = fmaf(r00, i0[b * 32 + c], acc[3]);
        }
    } else if (f == 3) {     // o1_c += (r11*m)*(u x v) ; o0_b += (r10*m)*(u.v)
        #pragma unroll 4
        for (int b = 0; b < 16; b++) {
            int gi = (b0 + b) * 32 + c;
            const float* g = ge + b * 12;
            float mask = g[8];
            float r10 = rs[b * 160 + 96 + c] * mask;
            float r11 = rs[b * 160 + 128 + c] * mask;
            float v0 = g_in1t[0][gi];
            float v1 = g_in1t[1][gi];
            float v2 = g_in1t[2][gi];
            float ux = g[0], uy = g[1], uz = g[2];
            acc[0] = fmaf(r11, uy * v2 - uz * v1, acc[0]);
            acc[1] = fmaf(r11, uz * v0 - ux * v2, acc[1]);
            acc[2] = fmaf(r11, ux * v1 - uy * v0, acc[2]);
            acc[3] = fmaf(r10, ux * v0 + uy * v1 + uz * v2, acc[3]);
        }
    } else {                 // o1_a += (r01*mask) * u * x0
        #pragma unroll 4
        for (int b = 0; b < 16; b++) {
            const float* g = ge + b * 12;
            float rx = rs[b * 160 + 32 + c] * g[8] * i0[b * 32 + c];
            acc[0] = fmaf(rx, g[0], acc[0]);
            acc[1] = fmaf(rx, g[1], acc[1]);
            acc[2] = fmaf(rx, g[2], acc[2]);
        }
    }
}

// 5 warps = 5 filters. 16-neighbor tiles, 1 barrier/tile, accumulate pipelined by 1 tile.
__global__ __launch_bounds__(160, 3) void tfn_kernel(Params p) {
    __shared__ float rbf_s[2][16 * 32];
    __shared__ float geo_s[3][16 * 12];
    __shared__ float in0_s[3][16 * 32];
    __shared__ float hid_s[16 * 160];
    __shared__ float rad_s[2][16 * 160];

    const int tid  = threadIdx.x;
    const int lane = tid & 31;
    const int f    = tid >> 5;
    const int a    = blockIdx.x;
    const int c    = lane;

    // ---- weights into packed registers ----
    u64 w1d[16], w2d[16];
    {
        const float4* w1p = (const float4*)(p.w1[f] + lane * 32);
        const float4* w2p = (const float4*)(p.w2[f] + lane * 32);
        #pragma unroll
        for (int k = 0; k < 8; k++) {
            float4 t1 = w1p[k];
            float4 t2 = w2p[k];
            w1d[2 * k]     = pk2(t1.x, t1.y);
            w1d[2 * k + 1] = pk2(t1.z, t1.w);
            w2d[2 * k]     = pk2(t2.x, t2.y);
            w2d[2 * k + 1] = pk2(t2.z, t2.w);
        }
    }
    const float b1r = p.b1[f][lane];
    const float b2r = p.b2[f][lane];

    float acc[5] = {0.f, 0.f, 0.f, 0.f, 0.f};

    // ---- preload tile 0 ----
    {
        const float* rsrc = p.rbf + (size_t)a * NNODES * 32;
        const float* gsrc = g_geo + (size_t)a * NNODES * 12;
        if (tid < 128) {
            cpa16(&rbf_s[0][tid * 4], rsrc + tid * 4);
            cpa16(&in0_s[0][tid * 4], p.in0 + tid * 4);
        } else {
            int g = tid - 128;                       // 0..31
            cpa16(&geo_s[0][g * 4], gsrc + g * 4);
            if (g < 16)
                cpa16(&geo_s[0][(g + 32) * 4], gsrc + (g + 32) * 4);
        }
        cpa_commit();
        cpa_wait0();
    }
    __syncthreads();

    int sw = 1;  // geo/in0 write slot for tile t+1 (= (t+1)%3)
    for (int t = 0; t < 32; t++) {
        const int cur = t & 1;

        // ---- prefetch tile t+1 (async) ----
        if (t < 31) {
            size_t tb = (size_t)(t + 1) * 16;
            const float* rsrc = p.rbf + ((size_t)a * NNODES + tb) * 32;
            const float* gsrc = g_geo + ((size_t)a * NNODES + tb) * 12;
            if (tid < 128) {
                cpa16(&rbf_s[cur ^ 1][tid * 4], rsrc + tid * 4);
                cpa16(&in0_s[sw][tid * 4], p.in0 + tb * 32 + tid * 4);
            } else {
                int g = tid - 128;
                cpa16(&geo_s[sw][g * 4], gsrc + g * 4);
                if (g < 16)
                    cpa16(&geo_s[sw][(g + 32) * 4], gsrc + (g + 32) * 4);
            }
        }
        cpa_commit();

        const float* rb = rbf_s[cur];

        // ---- stage1: hidden = relu(b1 + W1 @ rbf), packed f32x2 ----
        #pragma unroll 4
        for (int nb = 0; nb < 16; nb++) {
            const ulonglong2* x4 = (const ulonglong2*)(rb + nb * 32);
            u64 a2 = 0ull, b2 = 0ull;
            #pragma unroll
            for (int k = 0; k < 8; k++) {
                ulonglong2 x = x4[k];
                a2 = f2fma(w1d[2 * k],     x.x, a2);
                b2 = f2fma(w1d[2 * k + 1], x.y, b2);
            }
            float lo, hi;
            upk2(f2add(a2, b2), lo, hi);
            hid_s[nb * 160 + f * 32 + lane] = fmaxf(b1r + lo + hi, 0.f);
        }
        __syncwarp();

        // ---- stage2: rad = b2 + W2 @ hidden, packed f32x2 ----
        #pragma unroll 4
        for (int nb = 0; nb < 16; nb++) {
            const ulonglong2* h4 = (const ulonglong2*)(hid_s + nb * 160 + f * 32);
            u64 a2 = 0ull, b2 = 0ull;
            #pragma unroll
            for (int k = 0; k < 8; k++) {
                ulonglong2 x = h4[k];
                a2 = f2fma(w2d[2 * k],     x.x, a2);
                b2 = f2fma(w2d[2 * k + 1], x.y, b2);
            }
            float lo, hi;
            upk2(f2add(a2, b2), lo, hi);
            rad_s[cur][nb * 160 + f * 32 + lane] = b2r + lo + hi;
        }

        // ---- accumulate tile t-1 (pipelined) ----
        if (t > 0) {
            int sr = sw + 1; if (sr == 3) sr = 0;   // (t-1)%3
            do_acc(f, c, (t - 1) * 16, geo_s[sr], in0_s[sr], rad_s[cur ^ 1], acc);
        }

        cpa_wait0();
        __syncthreads();
        sw = (sw == 2) ? 0 : sw + 1;
    }

    // ---- tail: accumulate tile 31 (slot 31%3 == 1, rad buf 1) ----
    do_acc(f, c, 31 * 16, geo_s[1], in0_s[1], rad_s[1], acc);

    // ---- epilogue: each warp writes its own components ----
    float* out = p.out;
    if (f == 0) {          // o2_s  [1,a,c,:]
        size_t base = 180224 + (((size_t)(NNODES + a)) * 32 + c) * 5;
        out[base + 0] = acc[0]; out[base + 1] = acc[1]; out[base + 2] = acc[2];
        out[base + 3] = acc[3]; out[base + 4] = acc[4];
    } else if (f == 1) {   // o2_a  [0,a,c,:]
        size_t base = 180224 + (((size_t)a) * 32 + c) * 5;
        out[base + 0] = acc[0]; out[base + 1] = acc[1]; out[base + 2] = acc[2];
        out[base + 3] = acc[3]; out[base + 4] = acc[4];
    } else if (f == 2) {   // o1_s [1,...] + o0_s [0,...]
        size_t base = 32768 + (((size_t)(NNODES + a)) * 32 + c) * 3;
        out[base + 0] = acc[0]; out[base + 1] = acc[1]; out[base + 2] = acc[2];
        out[(size_t)a * 32 + c] = acc[3];
    } else if (f == 3) {   // o1_c [2,...] + o0_b [1,...]
        size_t base = 32768 + (((size_t)(2 * NNODES + a)) * 32 + c) * 3;
        out[base + 0] = acc[0]; out[base + 1] = acc[1]; out[base + 2] = acc[2];
        out[16384 + (size_t)a * 32 + c] = acc[3];
    } else {               // o1_a [0,...]
        size_t base = 32768 + (((size_t)a) * 32 + c) * 3;
        out[base + 0] = acc[0]; out[base + 1] = acc[1]; out[base + 2] = acc[2];
    }
}

extern "C" void kernel_launch(void* const* d_in, const int* in_sizes, int n_in,
                              void* d_out, int out_size) {
    Params p;
    p.in0 = (const float*)d_in[0];
    p.in1 = (const float*)d_in[1];
    p.in2 = (const float*)d_in[2];
    p.rbf = (const float*)d_in[3];
    p.rij = (const float*)d_in[4];
    for (int f = 0; f < 5; f++) {
        p.w1[f] = (const float*)d_in[5 + 4 * f];
        p.b1[f] = (const float*)d_in[6 + 4 * f];
        p.w2[f] = (const float*)d_in[7 + 4 * f];
        p.b2[f] = (const float*)d_in[8 + 4 * f];
    }
    p.out = (float*)d_out;

    prep_kernel<<<(NNODES * NNODES) / 256, 256>>>(p.rij, p.in1, p.in2);
    tfn_kernel<<<NNODES, 160>>>(p);
}

// round 9
// speedup vs baseline: 1.0732x; 1.0729x over previous
#include <cuda_runtime.h>
#include <cuda_bf16.h>
#include <math.h>
#include <stdint.h>

#define NNODES 512
#define EPSF 1e-8f

// static device scratch
__device__ __align__(16) float g_in1t[3][NNODES * 32];         // [i][b*32+c]
__device__ __align__(16) float g_in2t[5][NNODES * 32];         // [i][b*32+c]
__device__ __align__(16) float g_geo[(size_t)NNODES * NNODES * 12]; // pitch 12

struct Params {
    const float* __restrict__ in0;
    const float* __restrict__ in1;
    const float* __restrict__ in2;
    const float* __restrict__ rbf;
    const float* __restrict__ rij;
    const float* __restrict__ w1[5];
    const float* __restrict__ b1[5];
    const float* __restrict__ w2[5];
    const float* __restrict__ b2[5];
    float* __restrict__ out;
};

__device__ __forceinline__ void cpa16(void* dst, const void* src) {
    unsigned int d = (unsigned int)__cvta_generic_to_shared(dst);
    asm volatile("cp.async.cg.shared.global [%0], [%1], 16;" :: "r"(d), "l"(src));
}
__device__ __forceinline__ void cpa_commit() {
    asm volatile("cp.async.commit_group;");
}
__device__ __forceinline__ void cpa_wait0() {
    asm volatile("cp.async.wait_group 0;" ::: "memory");
}

__global__ __launch_bounds__(256) void prep_kernel(
    const float* __restrict__ rij,
    const float* __restrict__ in1,
    const float* __restrict__ in2)
{
    int idx = blockIdx.x * 256 + threadIdx.x;  // 0 .. N*N-1
    if (idx < NNODES * 32) {
        #pragma unroll
        for (int i = 0; i < 3; i++) g_in1t[i][idx] = in1[idx * 3 + i];
        #pragma unroll
        for (int i = 0; i < 5; i++) g_in2t[i][idx] = in2[idx * 5 + i];
    }
    const float inv_c2 = 0.28867513459481287f;  // 1/(2*sqrt(3))
    float rx = rij[idx * 3 + 0];
    float ry = rij[idx * 3 + 1];
    float rz = rij[idx * 3 + 2];
    float n2 = rx * rx + ry * ry + rz * rz;
    float nrm = sqrtf(n2);
    float invn = 1.f / (nrm + EPSF);
    float mask = (nrm >= EPSF) ? 1.f : 0.f;
    float ir2 = 1.f / fmaxf(n2, EPSF);
    float* g = g_geo + (size_t)idx * 12;
    g[0] = rx * invn; g[1] = ry * invn; g[2] = rz * invn;
    g[3] = rx * ry * ir2;
    g[4] = ry * rz * ir2;
    g[5] = (2.f * rz * rz - rx * rx - ry * ry) * ir2 * inv_c2;
    g[6] = rz * rx * ir2;
    g[7] = (rx * rx - ry * ry) * 0.5f * ir2;
    g[8] = mask;
    g[9] = 0.f; g[10] = 0.f; g[11] = 0.f;
}

// 5 warps = 5 filters. 8-neighbor tiles, cp.async double-buffered rbf/geo,
// 2 barriers per tile.
__global__ __launch_bounds__(160) void tfn_kernel(Params p) {
    __shared__ float rbf_s[2][8 * 32];   // [buf][b*32+r]
    __shared__ float geo_s[2][8 * 12];   // [buf][b*12+k]
    __shared__ float hid_s[8 * 160];     // [b][f*32+j]  warp-private slices
    __shared__ float rad_s[8 * 160];     // [b][f*32+c]

    const int tid  = threadIdx.x;
    const int lane = tid & 31;
    const int f    = tid >> 5;
    const int a    = blockIdx.x;
    const int c    = lane;

    // ---- weights into registers (lane = matrix row) ----
    float w1r[32], w2r[32];
    {
        const float4* w1p = (const float4*)(p.w1[f] + lane * 32);
        const float4* w2p = (const float4*)(p.w2[f] + lane * 32);
        #pragma unroll
        for (int k = 0; k < 8; k++) {
            float4 t1 = w1p[k];
            float4 t2 = w2p[k];
            w1r[4*k+0] = t1.x; w1r[4*k+1] = t1.y; w1r[4*k+2] = t1.z; w1r[4*k+3] = t1.w;
            w2r[4*k+0] = t2.x; w2r[4*k+1] = t2.y; w2r[4*k+2] = t2.z; w2r[4*k+3] = t2.w;
        }
    }
    const float b1r = p.b1[f][lane];
    const float b2r = p.b2[f][lane];

    float acc0 = 0.f, acc1 = 0.f, acc2 = 0.f, acc3 = 0.f, acc4 = 0.f;

    const float* rbase = p.rbf + (size_t)a * NNODES * 32;
    const float* gbase = g_geo + (size_t)a * NNODES * 12;

    // ---- preload tile 0 ----
    if (tid < 64) {
        cpa16(&rbf_s[0][tid * 4], rbase + tid * 4);
    } else if (tid < 88) {
        int g = tid - 64;            // 0..23 -> 24 x 16B = 8*12 floats
        cpa16(&geo_s[0][g * 4], gbase + g * 4);
    }
    cpa_commit();
    cpa_wait0();
    __syncthreads();

    for (int t = 0; t < 64; t++) {
        const int cur = t & 1;
        const int b0 = t * 8;

        // ---- async prefetch tile t+1 into buf cur^1 ----
        if (t < 63) {
            if (tid < 64) {
                cpa16(&rbf_s[cur ^ 1][tid * 4], rbase + (size_t)(b0 + 8) * 32 + tid * 4);
            } else if (tid < 88) {
                int g = tid - 64;
                cpa16(&geo_s[cur ^ 1][g * 4], gbase + (size_t)(b0 + 8) * 12 + g * 4);
            }
        }
        cpa_commit();

        const float* rb = rbf_s[cur];
        const float* ge = geo_s[cur];

        // ---- stage1: hidden = relu(b1 + W1 @ rbf) ----
        #pragma unroll 4
        for (int b = 0; b < 8; b++) {
            float s = b1r;
            const float4* x4 = (const float4*)(rb + b * 32);
            #pragma unroll
            for (int k = 0; k < 8; k++) {
                float4 x = x4[k];
                s = fmaf(w1r[4*k+0], x.x, s);
                s = fmaf(w1r[4*k+1], x.y, s);
                s = fmaf(w1r[4*k+2], x.z, s);
                s = fmaf(w1r[4*k+3], x.w, s);
            }
            hid_s[b * 160 + f * 32 + lane] = fmaxf(s, 0.f);
        }
        __syncwarp();  // stage2 of filter f reads only filter f's hidden slice

        // ---- stage2: rad = b2 + W2 @ hidden ----
        #pragma unroll 4
        for (int b = 0; b < 8; b++) {
            float s = b2r;
            const float4* h4 = (const float4*)(hid_s + b * 160 + f * 32);
            #pragma unroll
            for (int k = 0; k < 8; k++) {
                float4 x = h4[k];
                s = fmaf(w2r[4*k+0], x.x, s);
                s = fmaf(w2r[4*k+1], x.y, s);
                s = fmaf(w2r[4*k+2], x.z, s);
                s = fmaf(w2r[4*k+3], x.w, s);
            }
            rad_s[b * 160 + f * 32 + lane] = s;
        }
        __syncthreads();  // rad ready for cross-filter consumption

        // ---- accumulate (coalesced transposed global loads) ----
        if (f == 0) {
            // o2_s += r00 * in2
            #pragma unroll
            for (int b = 0; b < 8; b++) {
                int gi = (b0 + b) * 32 + c;
                float r00 = rad_s[b * 160 + c];
                acc0 = fmaf(r00, g_in2t[0][gi], acc0);
                acc1 = fmaf(r00, g_in2t[1][gi], acc1);
                acc2 = fmaf(r00, g_in2t[2][gi], acc2);
                acc3 = fmaf(r00, g_in2t[3][gi], acc3);
                acc4 = fmaf(r00, g_in2t[4][gi], acc4);
            }
        } else if (f == 1) {
            // o2_a += (r02*mask) * y2 * x0
            #pragma unroll
            for (int b = 0; b < 8; b++) {
                const float* g = ge + b * 12;
                float rx = rad_s[b * 160 + 64 + c] * g[8]
                         * p.in0[(size_t)(b0 + b) * 32 + c];
                acc0 = fmaf(rx, g[3], acc0);
                acc1 = fmaf(rx, g[4], acc1);
                acc2 = fmaf(rx, g[5], acc2);
                acc3 = fmaf(rx, g[6], acc3);
                acc4 = fmaf(rx, g[7], acc4);
            }
        } else if (f == 2) {
            // o1_s += r00 * in1 ; o0_s += r00 * in0
            #pragma unroll
            for (int b = 0; b < 8; b++) {
                int gi = (b0 + b) * 32 + c;
                float r00 = rad_s[b * 160 + c];
                acc0 = fmaf(r00, g_in1t[0][gi], acc0);
                acc1 = fmaf(r00, g_in1t[1][gi], acc1);
                acc2 = fmaf(r00, g_in1t[2][gi], acc2);
                acc3 = fmaf(r00, p.in0[gi], acc3);
            }
        } else if (f == 3) {
            // o1_c += (r11*m)*(u x v) ; o0_b += (r10*m)*(u.v)
            #pragma unroll
            for (int b = 0; b < 8; b++) {
                int gi = (b0 + b) * 32 + c;
                const float* g = ge + b * 12;
                float mask = g[8];
                float r10 = rad_s[b * 160 + 96 + c] * mask;
                float r11 = rad_s[b * 160 + 128 + c] * mask;
                float v0 = g_in1t[0][gi];
                float v1 = g_in1t[1][gi];
                float v2 = g_in1t[2][gi];
                float ux = g[0], uy = g[1], uz = g[2];
                acc0 = fmaf(r11, uy * v2 - uz * v1, acc0);
                acc1 = fmaf(r11, uz * v0 - ux * v2, acc1);
                acc2 = fmaf(r11, ux * v1 - uy * v0, acc2);
                acc3 = fmaf(r10, ux * v0 + uy * v1 + uz * v2, acc3);
            }
        } else {
            // o1_a += (r01*mask) * u * x0
            #pragma unroll
            for (int b = 0; b < 8; b++) {
                const float* g = ge + b * 12;
                float rx = rad_s[b * 160 + 32 + c] * g[8]
                         * p.in0[(size_t)(b0 + b) * 32 + c];
                acc0 = fmaf(rx, g[0], acc0);
                acc1 = fmaf(rx, g[1], acc1);
                acc2 = fmaf(rx, g[2], acc2);
            }
        }

        cpa_wait0();
        __syncthreads();  // next-tile rbf/geo landed; rad free for overwrite
    }

    // ---- epilogue: each warp writes its own components ----
    float* out = p.out;
    if (f == 0) {          // o2_s  [1,a,c,:]
        size_t base = 180224 + (((size_t)(NNODES + a)) * 32 + c) * 5;
        out[base + 0] = acc0; out[base + 1] = acc1; out[base + 2] = acc2;
        out[base + 3] = acc3; out[base + 4] = acc4;
    } else if (f == 1) {   // o2_a  [0,a,c,:]
        size_t base = 180224 + (((size_t)a) * 32 + c) * 5;
        out[base + 0] = acc0; out[base + 1] = acc1; out[base + 2] = acc2;
        out[base + 3] = acc3; out[base + 4] = acc4;
    } else if (f == 2) {   // o1_s [1,...] + o0_s [0,...]
        size_t base = 32768 + (((size_t)(NNODES + a)) * 32 + c) * 3;
        out[base + 0] = acc0; out[base + 1] = acc1; out[base + 2] = acc2;
        out[(size_t)a * 32 + c] = acc3;
    } else if (f == 3) {   // o1_c [2,...] + o0_b [1,...]
        size_t base = 32768 + (((size_t)(2 * NNODES + a)) * 32 + c) * 3;
        out[base + 0] = acc0; out[base + 1] = acc1; out[base + 2] = acc2;
        out[16384 + (size_t)a * 32 + c] = acc3;
    } else {               // o1_a [0,...]
        size_t base = 32768 + (((size_t)a) * 32 + c) * 3;
        out[base + 0] = acc0; out[base + 1] = acc1; out[base + 2] = acc2;
    }
}

extern "C" void kernel_launch(void* const* d_in, const int* in_sizes, int n_in,
                              void* d_out, int out_size) {
    Params p;
    p.in0 = (const float*)d_in[0];
    p.in1 = (const float*)d_in[1];
    p.in2 = (const float*)d_in[2];
    p.rbf = (const float*)d_in[3];
    p.rij = (const float*)d_in[4];
    for (int f = 0; f < 5; f++) {
        p.w1[f] = (const float*)d_in[5 + 4 * f];
        p.b1[f] = (const float*)d_in[6 + 4 * f];
        p.w2[f] = (const float*)d_in[7 + 4 * f];
        p.b2[f] = (const float*)d_in[8 + 4 * f];
    }
    p.out = (float*)d_out;

    prep_kernel<<<(NNODES * NNODES) / 256, 256>>>(p.rij, p.in1, p.in2);
    tfn_kernel<<<NNODES, 160>>>(p);
}

// round 10
// speedup vs baseline: 1.0802x; 1.0065x over previous
#include <cuda_runtime.h>
#include <cuda_bf16.h>
#include <math.h>
#include <stdint.h>

#define NNODES 512
#define EPSF 1e-8f
#define RADP 164      // rad_s row pitch (floats)

// static device scratch
__device__ __align__(16) float g_in1t[3][NNODES * 32];
__device__ __align__(16) float g_in2t[5][NNODES * 32];
__device__ __align__(16) float g_geo[(size_t)NNODES * NNODES * 12];
__device__ __align__(16) float g_b1frag[5120];   // [f][kt][nt][lane][2] tf32(W1^T) frags
__device__ __align__(16) float g_b2frag[5120];   // same for W2

struct Params {
    const float* __restrict__ in0;
    const float* __restrict__ in1;
    const float* __restrict__ in2;
    const float* __restrict__ rbf;
    const float* __restrict__ rij;
    const float* __restrict__ w1[5];
    const float* __restrict__ b1[5];
    const float* __restrict__ w2[5];
    const float* __restrict__ b2[5];
    float* __restrict__ out;
};

__device__ __forceinline__ unsigned tf32r(float x) {
    unsigned u;
    asm("cvt.rna.tf32.f32 %0, %1;" : "=r"(u) : "f"(x));
    return u;
}
__device__ __forceinline__ void mma8(float& c0, float& c1, float& c2, float& c3,
                                     uint4 a, uint2 b) {
    asm("mma.sync.aligned.m16n8k8.row.col.f32.tf32.tf32.f32 "
        "{%0,%1,%2,%3},{%4,%5,%6,%7},{%8,%9},{%0,%1,%2,%3};"
        : "+f"(c0), "+f"(c1), "+f"(c2), "+f"(c3)
        : "r"(a.x), "r"(a.y), "r"(a.z), "r"(a.w), "r"(b.x), "r"(b.y));
}
__device__ __forceinline__ void cpa16(void* dst, const void* src) {
    unsigned int d = (unsigned int)__cvta_generic_to_shared(dst);
    asm volatile("cp.async.cg.shared.global [%0], [%1], 16;" :: "r"(d), "l"(src));
}
__device__ __forceinline__ void cpa_commit() { asm volatile("cp.async.commit_group;"); }
__device__ __forceinline__ void cpa_wait0()  { asm volatile("cp.async.wait_group 0;" ::: "memory"); }

__global__ __launch_bounds__(256) void prep_kernel(
    const float* __restrict__ rij,
    const float* __restrict__ in1,
    const float* __restrict__ in2)
{
    int idx = blockIdx.x * 256 + threadIdx.x;
    if (idx < NNODES * 32) {
        #pragma unroll
        for (int i = 0; i < 3; i++) g_in1t[i][idx] = in1[idx * 3 + i];
        #pragma unroll
        for (int i = 0; i < 5; i++) g_in2t[i][idx] = in2[idx * 5 + i];
    }
    const float inv_c2 = 0.28867513459481287f;
    float rx = rij[idx * 3 + 0];
    float ry = rij[idx * 3 + 1];
    float rz = rij[idx * 3 + 2];
    float n2 = rx * rx + ry * ry + rz * rz;
    float nrm = sqrtf(n2);
    float invn = 1.f / (nrm + EPSF);
    float mask = (nrm >= EPSF) ? 1.f : 0.f;
    float ir2 = 1.f / fmaxf(n2, EPSF);
    float* g = g_geo + (size_t)idx * 12;
    g[0] = rx * invn; g[1] = ry * invn; g[2] = rz * invn;
    g[3] = rx * ry * ir2;
    g[4] = ry * rz * ir2;
    g[5] = (2.f * rz * rz - rx * rx - ry * ry) * ir2 * inv_c2;
    g[6] = rz * rx * ir2;
    g[7] = (rx * rx - ry * ry) * 0.5f * ir2;
    g[8] = mask;
    g[9] = 0.f; g[10] = 0.f; g[11] = 0.f;
}

// Build tf32 B-fragments for both stages. B[k][n] = W[n][k].
// frag: b0 = B[kt*8 + t][nt*8 + g], b1 = B[kt*8 + t + 4][nt*8 + g]
__global__ void prep_bfrag(Params p) {
    int idx = blockIdx.x * 512 + threadIdx.x;   // 0..5119
    if (idx >= 5120) return;
    int i    = idx & 1;
    int lane = (idx >> 1) & 31;
    int nt   = (idx >> 6) & 3;
    int kt   = (idx >> 8) & 3;
    int f    = idx >> 10;
    int g = lane >> 2, t = lane & 3;
    int rw = nt * 8 + g;            // W row (output dim)
    int cw = kt * 8 + t + 4 * i;    // W col (input dim)
    g_b1frag[idx] = __uint_as_float(tf32r(p.w1[f][rw * 32 + cw]));
    g_b2frag[idx] = __uint_as_float(tf32r(p.w2[f][rw * 32 + cw]));
}

// 5 warps = 5 filters, 16-neighbor tiles, tensor-core radial MLP.
__global__ __launch_bounds__(160) void tfn_kernel(Params p) {
    __shared__ float raw_s[2][512];       // raw rbf tile [nb*32+r]
    __shared__ float geo_s[2][192];       // [b*12+k]
    __shared__ float As[2][512];          // A frags hi/lo: [kt*128 + lane*4 + idx]
    __shared__ float Hs[5][2][512];       // per-filter H frags hi/lo
    __shared__ float rad_s[16 * RADP];    // [b*RADP + f*32 + c]

    const int tid  = threadIdx.x;
    const int lane = tid & 31;
    const int f    = tid >> 5;
    const int a    = blockIdx.x;
    const int c    = lane;
    const int g    = lane >> 2;
    const int t4   = lane & 3;

    // ---- resident weight fragments (tf32 hi) ----
    uint2 b1h[4][4], b2h[4][4];
    #pragma unroll
    for (int kt = 0; kt < 4; kt++)
        #pragma unroll
        for (int nt = 0; nt < 4; nt++) {
            int base = (((f * 4 + kt) * 4 + nt) * 64) + lane * 2;
            float2 v1 = *(const float2*)&g_b1frag[base];
            float2 v2 = *(const float2*)&g_b2frag[base];
            b1h[kt][nt] = make_uint2(__float_as_uint(v1.x), __float_as_uint(v1.y));
            b2h[kt][nt] = make_uint2(__float_as_uint(v2.x), __float_as_uint(v2.y));
        }
    // ---- biases for this thread's fragment columns ----
    float b1v[4][2], b2v[4][2];
    #pragma unroll
    for (int nt = 0; nt < 4; nt++) {
        b1v[nt][0] = p.b1[f][nt * 8 + 2 * t4];
        b1v[nt][1] = p.b1[f][nt * 8 + 2 * t4 + 1];
        b2v[nt][0] = p.b2[f][nt * 8 + 2 * t4];
        b2v[nt][1] = p.b2[f][nt * 8 + 2 * t4 + 1];
    }

    float acc0 = 0.f, acc1 = 0.f, acc2 = 0.f, acc3 = 0.f, acc4 = 0.f;

    const float* rbase = p.rbf + (size_t)a * NNODES * 32;
    const float* gbase = g_geo + (size_t)a * NNODES * 12;

    // ---- preload tile 0 ----
    if (tid < 128) {
        cpa16(&raw_s[0][tid * 4], rbase + tid * 4);
    } else {
        int q = tid - 128;
        cpa16(&geo_s[0][q * 4], gbase + q * 4);
        if (q < 16) cpa16(&geo_s[0][(q + 32) * 4], gbase + (q + 32) * 4);
    }
    cpa_commit();
    cpa_wait0();
    __syncthreads();

    for (int t = 0; t < 32; t++) {
        const int cur = t & 1;
        const int b0 = t * 16;

        // ---- prefetch tile t+1 ----
        if (t < 31) {
            const float* rsrc = rbase + (size_t)(b0 + 16) * 32;
            const float* gsrc = gbase + (size_t)(b0 + 16) * 12;
            if (tid < 128) {
                cpa16(&raw_s[cur ^ 1][tid * 4], rsrc + tid * 4);
            } else {
                int q = tid - 128;
                cpa16(&geo_s[cur ^ 1][q * 4], gsrc + q * 4);
                if (q < 16) cpa16(&geo_s[cur ^ 1][(q + 32) * 4], gsrc + (q + 32) * 4);
            }
        }
        cpa_commit();

        // ---- split: raw rbf -> tf32 hi/lo in A-fragment layout ----
        if (tid < 128) {
            float4 rv = *(const float4*)&raw_s[cur][tid * 4];
            int nb = tid >> 3;
            int r0 = (tid & 7) * 4;
            float xv[4] = {rv.x, rv.y, rv.z, rv.w};
            #pragma unroll
            for (int j = 0; j < 4; j++) {
                int r = r0 + j;
                unsigned hb = tf32r(xv[j]);
                float hf = __uint_as_float(hb);
                unsigned lb = tf32r(xv[j] - hf);
                int kt = r >> 3, rm = r & 7;
                int tq = rm & 3, dl = rm >> 2;
                int off = kt * 128 + ((nb & 7) * 4 + tq) * 4 + (nb >> 3) + 2 * dl;
                As[0][off] = hf;
                As[1][off] = __uint_as_float(lb);
            }
        }
        __syncthreads();

        // ---- stage1: H = relu(b1 + rbf @ W1^T) via tf32 mma (2-term A-split) ----
        {
            float acc[4][4];
            #pragma unroll
            for (int nt = 0; nt < 4; nt++) { acc[nt][0]=0.f; acc[nt][1]=0.f; acc[nt][2]=0.f; acc[nt][3]=0.f; }
            #pragma unroll
            for (int kt = 0; kt < 4; kt++) {
                uint4 ah = *(const uint4*)&As[0][kt * 128 + lane * 4];
                uint4 al = *(const uint4*)&As[1][kt * 128 + lane * 4];
                #pragma unroll
                for (int nt = 0; nt < 4; nt++) {
                    mma8(acc[nt][0], acc[nt][1], acc[nt][2], acc[nt][3], ah, b1h[kt][nt]);
                    mma8(acc[nt][0], acc[nt][1], acc[nt][2], acc[nt][3], al, b1h[kt][nt]);
                }
            }
            // epilogue: bias+relu, split hi/lo, store to H frag layout (kt' = nt)
            float* Hh = Hs[f][0];
            float* Hl = Hs[f][1];
            #pragma unroll
            for (int nt = 0; nt < 4; nt++) {
                #pragma unroll
                for (int e = 0; e < 4; e++) {
                    int row = g + (e >= 2 ? 8 : 0);
                    int dc  = e & 1;                 // col = nt*8 + 2*t4 + dc
                    float h = fmaxf(acc[nt][e] + b1v[nt][dc], 0.f);
                    unsigned hb = tf32r(h);
                    float hf = __uint_as_float(hb);
                    unsigned lb = tf32r(h - hf);
                    int rm = 2 * t4 + dc;
                    int tq = rm & 3, dl = rm >> 2;
                    int off = nt * 128 + ((row & 7) * 4 + tq) * 4 + (row >> 3) + 2 * dl;
                    Hh[off] = hf;
                    Hl[off] = __uint_as_float(lb);
                }
            }
        }
        __syncwarp();

        // ---- stage2: rad = b2 + H @ W2^T ----
        {
            float acc[4][4];
            #pragma unroll
            for (int nt = 0; nt < 4; nt++) { acc[nt][0]=0.f; acc[nt][1]=0.f; acc[nt][2]=0.f; acc[nt][3]=0.f; }
            const float* Hh = Hs[f][0];
            const float* Hl = Hs[f][1];
            #pragma unroll
            for (int kt = 0; kt < 4; kt++) {
                uint4 ah = *(const uint4*)&Hh[kt * 128 + lane * 4];
                uint4 al = *(const uint4*)&Hl[kt * 128 + lane * 4];
                #pragma unroll
                for (int nt = 0; nt < 4; nt++) {
                    mma8(acc[nt][0], acc[nt][1], acc[nt][2], acc[nt][3], ah, b2h[kt][nt]);
                    mma8(acc[nt][0], acc[nt][1], acc[nt][2], acc[nt][3], al, b2h[kt][nt]);
                }
            }
            // epilogue: bias, store rad_s[row][f*32 + c]
            #pragma unroll
            for (int nt = 0; nt < 4; nt++) {
                float r0v = acc[nt][0] + b2v[nt][0];
                float r1v = acc[nt][1] + b2v[nt][1];
                float r2v = acc[nt][2] + b2v[nt][0];
                float r3v = acc[nt][3] + b2v[nt][1];
                int colw = f * 32 + nt * 8 + 2 * t4;
                *(float2*)&rad_s[g * RADP + colw]       = make_float2(r0v, r1v);
                *(float2*)&rad_s[(g + 8) * RADP + colw] = make_float2(r2v, r3v);
            }
        }
        __syncthreads();

        // ---- accumulate over 16 neighbors ----
        const float* ge = geo_s[cur];
        if (f == 0) {
            #pragma unroll 4
            for (int b = 0; b < 16; b++) {
                int gi = (b0 + b) * 32 + c;
                float r00 = rad_s[b * RADP + c];
                acc0 = fmaf(r00, g_in2t[0][gi], acc0);
                acc1 = fmaf(r00, g_in2t[1][gi], acc1);
                acc2 = fmaf(r00, g_in2t[2][gi], acc2);
                acc3 = fmaf(r00, g_in2t[3][gi], acc3);
                acc4 = fmaf(r00, g_in2t[4][gi], acc4);
            }
        } else if (f == 1) {
            #pragma unroll 4
            for (int b = 0; b < 16; b++) {
                const float* gg = ge + b * 12;
                float rx = rad_s[b * RADP + 64 + c] * gg[8]
                         * p.in0[(size_t)(b0 + b) * 32 + c];
                acc0 = fmaf(rx, gg[3], acc0);
                acc1 = fmaf(rx, gg[4], acc1);
                acc2 = fmaf(rx, gg[5], acc2);
                acc3 = fmaf(rx, gg[6], acc3);
                acc4 = fmaf(rx, gg[7], acc4);
            }
        } else if (f == 2) {
            #pragma unroll 4
            for (int b = 0; b < 16; b++) {
                int gi = (b0 + b) * 32 + c;
                float r00 = rad_s[b * RADP + c];
                acc0 = fmaf(r00, g_in1t[0][gi], acc0);
                acc1 = fmaf(r00, g_in1t[1][gi], acc1);
                acc2 = fmaf(r00, g_in1t[2][gi], acc2);
                acc3 = fmaf(r00, p.in0[gi], acc3);
            }
        } else if (f == 3) {
            #pragma unroll 4
            for (int b = 0; b < 16; b++) {
                int gi = (b0 + b) * 32 + c;
                const float* gg = ge + b * 12;
                float mask = gg[8];
                float r10 = rad_s[b * RADP + 96 + c] * mask;
                float r11 = rad_s[b * RADP + 128 + c] * mask;
                float v0 = g_in1t[0][gi];
                float v1 = g_in1t[1][gi];
                float v2 = g_in1t[2][gi];
                float ux = gg[0], uy = gg[1], uz = gg[2];
                acc0 = fmaf(r11, uy * v2 - uz * v1, acc0);
                acc1 = fmaf(r11, uz * v0 - ux * v2, acc1);
                acc2 = fmaf(r11, ux * v1 - uy * v0, acc2);
                acc3 = fmaf(r10, ux * v0 + uy * v1 + uz * v2, acc3);
            }
        } else {
            #pragma unroll 4
            for (int b = 0; b < 16; b++) {
                const float* gg = ge + b * 12;
                float rx = rad_s[b * RADP + 32 + c] * gg[8]
                         * p.in0[(size_t)(b0 + b) * 32 + c];
                acc0 = fmaf(rx, gg[0], acc0);
                acc1 = fmaf(rx, gg[1], acc1);
                acc2 = fmaf(rx, gg[2], acc2);
            }
        }

        cpa_wait0();
        __syncthreads();
    }

    // ---- output epilogue ----
    float* out = p.out;
    if (f == 0) {
        size_t base = 180224 + (((size_t)(NNODES + a)) * 32 + c) * 5;
        out[base + 0] = acc0; out[base + 1] = acc1; out[base + 2] = acc2;
        out[base + 3] = acc3; out[base + 4] = acc4;
    } else if (f == 1) {
        size_t base = 180224 + (((size_t)a) * 32 + c) * 5;
        out[base + 0] = acc0; out[base + 1] = acc1; out[base + 2] = acc2;
        out[base + 3] = acc3; out[base + 4] = acc4;
    } else if (f == 2) {
        size_t base = 32768 + (((size_t)(NNODES + a)) * 32 + c) * 3;
        out[base + 0] = acc0; out[base + 1] = acc1; out[base + 2] = acc2;
        out[(size_t)a * 32 + c] = acc3;
    } else if (f == 3) {
        size_t base = 32768 + (((size_t)(2 * NNODES + a)) * 32 + c) * 3;
        out[base + 0] = acc0; out[base + 1] = acc1; out[base + 2] = acc2;
        out[16384 + (size_t)a * 32 + c] = acc3;
    } else {
        size_t base = 32768 + (((size_t)a) * 32 + c) * 3;
        out[base + 0] = acc0; out[base + 1] = acc1; out[base + 2] = acc2;
    }
}

extern "C" void kernel_launch(void* const* d_in, const int* in_sizes, int n_in,
                              void* d_out, int out_size) {
    Params p;
    p.in0 = (const float*)d_in[0];
    p.in1 = (const float*)d_in[1];
    p.in2 = (const float*)d_in[2];
    p.rbf = (const float*)d_in[3];
    p.rij = (const float*)d_in[4];
    for (int f = 0; f < 5; f++) {
        p.w1[f] = (const float*)d_in[5 + 4 * f];
        p.b1[f] = (const float*)d_in[6 + 4 * f];
        p.w2[f] = (const float*)d_in[7 + 4 * f];
        p.b2[f] = (const float*)d_in[8 + 4 * f];
    }
    p.out = (float*)d_out;

    prep_kernel<<<(NNODES * NNODES) / 256, 256>>>(p.rij, p.in1, p.in2);
    prep_bfrag<<<10, 512>>>(p);
    tfn_kernel<<<NNODES, 160>>>(p);
}